// round 1
// baseline (speedup 1.0000x reference)
#include <cuda_runtime.h>
#include <cstdint>
#include <cstddef>

#define BATCH 8
#define CDIM 256
#define CIDIM 128
#define NPIX 4096

// Scratch (allocation-free rule: __device__ globals)
static __device__ float g_theta[BATCH * CIDIM * NPIX];
static __device__ float g_phi  [BATCH * CIDIM * NPIX];
static __device__ float g_gv   [BATCH * CIDIM * NPIX];
static __device__ float g_y    [BATCH * NPIX * CIDIM];   // [B][N][CI]

// ---- packed fp32x2 helpers (sm_103a FFMA2 path, only reachable via PTX) ----
__device__ __forceinline__ unsigned long long pack2(float lo, float hi) {
    unsigned long long r;
    asm("mov.b64 %0, {%1, %2};" : "=l"(r) : "f"(lo), "f"(hi));
    return r;
}
__device__ __forceinline__ float2 unpack2(unsigned long long v) {
    float2 r;
    asm("mov.b64 {%0, %1}, %2;" : "=f"(r.x), "=f"(r.y) : "l"(v));
    return r;
}
__device__ __forceinline__ unsigned long long fma2(unsigned long long a,
                                                   unsigned long long b,
                                                   unsigned long long c) {
    unsigned long long d;
    asm("fma.rn.f32x2 %0, %1, %2, %3;" : "=l"(d) : "l"(a), "l"(b), "l"(c));
    return d;
}

// ================= projection: {theta,phi,g} = W @ x + b =================
// grid (N/64, 6, B), 256 thr, tile 64(o) x 64(n), k-chunk 32
__global__ __launch_bounds__(256) void proj_kernel(
    const float* __restrict__ x,
    const float* __restrict__ th_w, const float* __restrict__ th_b,
    const float* __restrict__ ph_w, const float* __restrict__ ph_b,
    const float* __restrict__ gw,   const float* __restrict__ gb)
{
    __shared__ float Ws[32][68];
    __shared__ float Xs[32][68];
    const int bb = blockIdx.z;
    const int ot = blockIdx.y;
    const int n0 = blockIdx.x * 64;
    const int tid = threadIdx.x;
    const int tx = tid & 15, ty = tid >> 4;

    const float* W; const float* bias; float* outp; int o0;
    if (ot < 2)      { W = th_w; bias = th_b; outp = g_theta; o0 = ot * 64; }
    else if (ot < 4) { W = ph_w; bias = ph_b; outp = g_phi;   o0 = (ot - 2) * 64; }
    else             { W = gw;   bias = gb;   outp = g_gv;    o0 = (ot - 4) * 64; }

    float acc[4][4] = {};
    for (int c0 = 0; c0 < CDIM; c0 += 32) {
        __syncthreads();
        for (int idx = tid; idx < 64 * 32; idx += 256) {
            int o = idx >> 5, c = idx & 31;
            Ws[c][o] = W[(o0 + o) * CDIM + c0 + c];
        }
        for (int idx = tid; idx < 32 * 64; idx += 256) {
            int c = idx >> 6, n = idx & 63;
            Xs[c][n] = x[((size_t)(bb * CDIM + c0 + c)) * NPIX + n0 + n];
        }
        __syncthreads();
        #pragma unroll
        for (int k = 0; k < 32; k++) {
            float4 wv = *(const float4*)&Ws[k][ty * 4];
            float4 xv = *(const float4*)&Xs[k][tx * 4];
            float wr[4] = {wv.x, wv.y, wv.z, wv.w};
            float xr[4] = {xv.x, xv.y, xv.z, xv.w};
            #pragma unroll
            for (int i = 0; i < 4; i++)
                #pragma unroll
                for (int j = 0; j < 4; j++)
                    acc[i][j] += wr[i] * xr[j];
        }
    }
    #pragma unroll
    for (int i = 0; i < 4; i++) {
        int o = o0 + ty * 4 + i;
        float bv = bias[o];
        float4 st = make_float4(acc[i][0] + bv, acc[i][1] + bv,
                                acc[i][2] + bv, acc[i][3] + bv);
        *(float4*)&outp[((size_t)(bb * CIDIM + o)) * NPIX + n0 + tx * 4] = st;
    }
}

// ================= flash attention (no-max softmax, fp32) =================
#define TI 64
#define TJ 64
#define DD 128
#define SVROW 132
#define SPROW 68
#define ATTN_SMEM_FLOATS (DD*TI + DD*TJ + TJ*SVROW + TI*SPROW + TI)
#define ATTN_SMEM_BYTES  (ATTN_SMEM_FLOATS * 4)

__global__ __launch_bounds__(256, 1) void attn_kernel()
{
    extern __shared__ float sm[];
    float* Qs   = sm;                    // [DD][TI]  c-major
    float* Ks   = Qs + DD * TI;          // [DD][TJ]  c-major
    float* Vs   = Ks + DD * TJ;          // [TJ][SVROW]  j-major
    float* Ps   = Vs + TJ * SVROW;       // [TI][SPROW]
    float* denr = Ps + TI * SPROW;       // [TI]

    const int bb = blockIdx.y;
    const int i0 = blockIdx.x * TI;
    const int tid = threadIdx.x;
    const int tx = tid & 15, ty = tid >> 4;

    // load Q tile once (coalesced float4)
    {
        const float4* src = (const float4*)&g_theta[(size_t)bb * CIDIM * NPIX];
        for (int idx = tid; idx < DD * TI / 4; idx += 256) {
            int c = idx >> 4, i4 = idx & 15;
            ((float4*)Qs)[idx] = src[(c * NPIX + i0) / 4 + i4];
        }
    }
    if (tid < TI) denr[tid] = 0.f;

    unsigned long long o2[4][4];  // rows ty*4+i, col-pairs at tx*8
    #pragma unroll
    for (int i = 0; i < 4; i++)
        #pragma unroll
        for (int j = 0; j < 4; j++) o2[i][j] = 0ull;
    float dacc[4] = {0.f, 0.f, 0.f, 0.f};

    for (int jt = 0; jt < NPIX / TJ; jt++) {
        const int j0 = jt * TJ;
        __syncthreads();     // prev PV done -> safe to overwrite Ks/Vs
        {
            const float4* src = (const float4*)&g_phi[(size_t)bb * CIDIM * NPIX];
            for (int idx = tid; idx < DD * TJ / 4; idx += 256) {
                int c = idx >> 4, j4 = idx & 15;
                ((float4*)Ks)[idx] = src[(c * NPIX + j0) / 4 + j4];
            }
        }
        {
            const float4* src = (const float4*)&g_gv[(size_t)bb * CIDIM * NPIX];
            for (int idx = tid; idx < DD * TJ / 4; idx += 256) {
                int c = idx >> 4, j4 = idx & 15;
                float4 v = src[(c * NPIX + j0) / 4 + j4];
                int j = j4 * 4;
                Vs[(j + 0) * SVROW + c] = v.x;
                Vs[(j + 1) * SVROW + c] = v.y;
                Vs[(j + 2) * SVROW + c] = v.z;
                Vs[(j + 3) * SVROW + c] = v.w;
            }
        }
        __syncthreads();

        // S = Q^T K : rows ty*4 + {0..3} (as 2 packed pairs), cols tx*4 + {0..3}
        unsigned long long acc2[2][4];
        #pragma unroll
        for (int a = 0; a < 2; a++)
            #pragma unroll
            for (int j = 0; j < 4; j++) acc2[a][j] = 0ull;

        #pragma unroll 4
        for (int c = 0; c < DD; c++) {
            const unsigned long long* qrow =
                (const unsigned long long*)&Qs[c * TI + ty * 4];
            unsigned long long q01 = qrow[0];
            unsigned long long q23 = qrow[1];
            float4 kv = *(const float4*)&Ks[c * TJ + tx * 4];
            unsigned long long k0 = pack2(kv.x, kv.x);
            unsigned long long k1 = pack2(kv.y, kv.y);
            unsigned long long k2 = pack2(kv.z, kv.z);
            unsigned long long k3 = pack2(kv.w, kv.w);
            acc2[0][0] = fma2(q01, k0, acc2[0][0]);
            acc2[0][1] = fma2(q01, k1, acc2[0][1]);
            acc2[0][2] = fma2(q01, k2, acc2[0][2]);
            acc2[0][3] = fma2(q01, k3, acc2[0][3]);
            acc2[1][0] = fma2(q23, k0, acc2[1][0]);
            acc2[1][1] = fma2(q23, k1, acc2[1][1]);
            acc2[1][2] = fma2(q23, k2, acc2[1][2]);
            acc2[1][3] = fma2(q23, k3, acc2[1][3]);
        }

        // P = exp(S); accumulate row sums; stage P to smem
        #pragma unroll
        for (int rp = 0; rp < 2; rp++) {
            float e0[4], e1[4];
            #pragma unroll
            for (int jc = 0; jc < 4; jc++) {
                float2 s = unpack2(acc2[rp][jc]);
                e0[jc] = __expf(s.x);
                e1[jc] = __expf(s.y);
            }
            dacc[2 * rp]     += e0[0] + e0[1] + e0[2] + e0[3];
            dacc[2 * rp + 1] += e1[0] + e1[1] + e1[2] + e1[3];
            int r0 = ty * 4 + 2 * rp;
            *(float4*)&Ps[r0 * SPROW + tx * 4] =
                make_float4(e0[0], e0[1], e0[2], e0[3]);
            *(float4*)&Ps[(r0 + 1) * SPROW + tx * 4] =
                make_float4(e1[0], e1[1], e1[2], e1[3]);
        }
        __syncthreads();

        // O += P @ V : rows ty*4+{0..3}, cols tx*8+{0..7} (4 packed pairs)
        #pragma unroll 2
        for (int j = 0; j < TJ; j++) {
            float p0 = Ps[(ty * 4 + 0) * SPROW + j];
            float p1 = Ps[(ty * 4 + 1) * SPROW + j];
            float p2 = Ps[(ty * 4 + 2) * SPROW + j];
            float p3 = Ps[(ty * 4 + 3) * SPROW + j];
            const unsigned long long* vr =
                (const unsigned long long*)&Vs[j * SVROW + tx * 8];
            unsigned long long v0 = vr[0], v1 = vr[1], v2 = vr[2], v3 = vr[3];
            unsigned long long pp0 = pack2(p0, p0);
            unsigned long long pp1 = pack2(p1, p1);
            unsigned long long pp2 = pack2(p2, p2);
            unsigned long long pp3 = pack2(p3, p3);
            o2[0][0] = fma2(pp0, v0, o2[0][0]);
            o2[0][1] = fma2(pp0, v1, o2[0][1]);
            o2[0][2] = fma2(pp0, v2, o2[0][2]);
            o2[0][3] = fma2(pp0, v3, o2[0][3]);
            o2[1][0] = fma2(pp1, v0, o2[1][0]);
            o2[1][1] = fma2(pp1, v1, o2[1][1]);
            o2[1][2] = fma2(pp1, v2, o2[1][2]);
            o2[1][3] = fma2(pp1, v3, o2[1][3]);
            o2[2][0] = fma2(pp2, v0, o2[2][0]);
            o2[2][1] = fma2(pp2, v1, o2[2][1]);
            o2[2][2] = fma2(pp2, v2, o2[2][2]);
            o2[2][3] = fma2(pp2, v3, o2[2][3]);
            o2[3][0] = fma2(pp3, v0, o2[3][0]);
            o2[3][1] = fma2(pp3, v1, o2[3][1]);
            o2[3][2] = fma2(pp3, v2, o2[3][2]);
            o2[3][3] = fma2(pp3, v3, o2[3][3]);
        }
    }

    // reduce denominators across tx, then normalize + store Y [B][N][CI]
    #pragma unroll
    for (int i = 0; i < 4; i++)
        atomicAdd(&denr[ty * 4 + i], dacc[i]);
    __syncthreads();

    #pragma unroll
    for (int i = 0; i < 4; i++) {
        int r = ty * 4 + i;
        float inv = 1.0f / denr[r];
        float2 a0 = unpack2(o2[i][0]);
        float2 a1 = unpack2(o2[i][1]);
        float2 a2 = unpack2(o2[i][2]);
        float2 a3 = unpack2(o2[i][3]);
        float* dst = &g_y[(((size_t)bb * NPIX) + i0 + r) * CIDIM + tx * 8];
        *(float4*)dst       = make_float4(a0.x * inv, a0.y * inv, a1.x * inv, a1.y * inv);
        *(float4*)(dst + 4) = make_float4(a2.x * inv, a2.y * inv, a3.x * inv, a3.y * inv);
    }
}

// ================= out = W_w @ y + W_b + x =================
// grid (N/64, C/64, B), 256 thr, contraction K = CI = 128 in 2 chunks of 64
__global__ __launch_bounds__(256) void outproj_kernel(
    const float* __restrict__ Ww, const float* __restrict__ Wb,
    const float* __restrict__ x, float* __restrict__ out)
{
    __shared__ float As[64][68];   // [k][c]
    __shared__ float Ys[64][68];   // [k][n]
    const int bb = blockIdx.z;
    const int c0 = blockIdx.y * 64;
    const int n0 = blockIdx.x * 64;
    const int tid = threadIdx.x;
    const int tx = tid & 15, ty = tid >> 4;

    float acc[4][4] = {};
    for (int k0 = 0; k0 < CIDIM; k0 += 64) {
        __syncthreads();
        for (int idx = tid; idx < 64 * 64; idx += 256) {
            int r = idx >> 6, k = idx & 63;
            As[k][r] = Ww[(c0 + r) * CIDIM + k0 + k];
        }
        for (int idx = tid; idx < 64 * 64; idx += 256) {
            int n = idx >> 6, k = idx & 63;
            Ys[k][n] = g_y[(((size_t)bb * NPIX) + n0 + n) * CIDIM + k0 + k];
        }
        __syncthreads();
        #pragma unroll 8
        for (int k = 0; k < 64; k++) {
            float4 av = *(const float4*)&As[k][ty * 4];
            float4 yv = *(const float4*)&Ys[k][tx * 4];
            float ar[4] = {av.x, av.y, av.z, av.w};
            float yr[4] = {yv.x, yv.y, yv.z, yv.w};
            #pragma unroll
            for (int i = 0; i < 4; i++)
                #pragma unroll
                for (int j = 0; j < 4; j++)
                    acc[i][j] += ar[i] * yr[j];
        }
    }
    #pragma unroll
    for (int i = 0; i < 4; i++) {
        int c = c0 + ty * 4 + i;
        float bv = Wb[c];
        size_t base = (((size_t)bb * CDIM) + c) * NPIX + n0 + tx * 4;
        float4 xv = *(const float4*)&x[base];
        float4 st = make_float4(acc[i][0] + bv + xv.x, acc[i][1] + bv + xv.y,
                                acc[i][2] + bv + xv.z, acc[i][3] + bv + xv.w);
        *(float4*)&out[base] = st;
    }
}

extern "C" void kernel_launch(void* const* d_in, const int* in_sizes, int n_in,
                              void* d_out, int out_size) {
    const float* x    = (const float*)d_in[0];
    const float* g_w  = (const float*)d_in[1];
    const float* g_b  = (const float*)d_in[2];
    const float* th_w = (const float*)d_in[3];
    const float* th_b = (const float*)d_in[4];
    const float* ph_w = (const float*)d_in[5];
    const float* ph_b = (const float*)d_in[6];
    const float* W_w  = (const float*)d_in[7];
    const float* W_b  = (const float*)d_in[8];
    float* out = (float*)d_out;

    // idempotent; legal outside/inside graph capture (not a stream op)
    cudaFuncSetAttribute(attn_kernel,
                         cudaFuncAttributeMaxDynamicSharedMemorySize,
                         ATTN_SMEM_BYTES);

    proj_kernel<<<dim3(NPIX / 64, 6, BATCH), 256>>>(x, th_w, th_b, ph_w, ph_b, g_w, g_b);
    attn_kernel<<<dim3(NPIX / TI, BATCH), 256, ATTN_SMEM_BYTES>>>();
    outproj_kernel<<<dim3(NPIX / 64, CDIM / 64, BATCH), 256>>>(W_w, W_b, x, out);
}

// round 4
// speedup vs baseline: 3.9245x; 3.9245x over previous
#include <cuda_runtime.h>
#include <cuda_bf16.h>
#include <cstdint>
#include <cstddef>

#define BATCH 8
#define CDIM 256
#define CIDIM 128
#define NPIX 4096
#define QT 128          // queries per CTA
#define JT 64           // keys per iteration
#define NJT (NPIX / JT)

// ---------------- scratch (__device__ globals; no allocation) ----------------
static __device__ __nv_bfloat16 g_th_h[BATCH * NPIX * CIDIM];  // [B][N][CI]
static __device__ __nv_bfloat16 g_th_l[BATCH * NPIX * CIDIM];
static __device__ __nv_bfloat16 g_ph_h[BATCH * NPIX * CIDIM];  // [B][N][CI]
static __device__ __nv_bfloat16 g_ph_l[BATCH * NPIX * CIDIM];
static __device__ __nv_bfloat16 g_gm_h[BATCH * CIDIM * NPIX];  // [B][CI][N]
static __device__ __nv_bfloat16 g_gm_l[BATCH * CIDIM * NPIX];
static __device__ float         g_y   [BATCH * NPIX * CIDIM];  // [B][N][CI]

// ---------------- PTX helpers (all family-portable: sm_80+ instructions) -----
__device__ __forceinline__ uint32_t smem_to_u32(const void* p) {
    uint32_t a;
    asm("{ .reg .u64 t; cvta.to.shared.u64 t, %1; cvt.u32.u64 %0, t; }"
        : "=r"(a) : "l"(p));
    return a;
}
__device__ __forceinline__ void cp16(uint32_t dst, const void* src) {
    asm volatile("cp.async.cg.shared.global [%0], [%1], 16;" :: "r"(dst), "l"(src) : "memory");
}
#define CP_COMMIT() asm volatile("cp.async.commit_group;" ::: "memory")
#define CP_WAIT1()  asm volatile("cp.async.wait_group 1;" ::: "memory")

__device__ __forceinline__ void ldsm4(uint32_t a, uint32_t& r0, uint32_t& r1,
                                      uint32_t& r2, uint32_t& r3) {
    asm volatile("ldmatrix.sync.aligned.m8n8.x4.shared.b16 {%0,%1,%2,%3}, [%4];"
                 : "=r"(r0), "=r"(r1), "=r"(r2), "=r"(r3) : "r"(a));
}
__device__ __forceinline__ void mma16816(float* d, const uint32_t* a,
                                         uint32_t b0, uint32_t b1) {
    asm volatile("mma.sync.aligned.m16n8k16.row.col.f32.bf16.bf16.f32 "
                 "{%0,%1,%2,%3}, {%4,%5,%6,%7}, {%8,%9}, {%0,%1,%2,%3};"
                 : "+f"(d[0]), "+f"(d[1]), "+f"(d[2]), "+f"(d[3])
                 : "r"(a[0]), "r"(a[1]), "r"(a[2]), "r"(a[3]), "r"(b0), "r"(b1));
}
__device__ __forceinline__ uint32_t packbf2(float lo, float hi) {
    uint32_t r;
    asm("cvt.rn.satfinite.bf16x2.f32 %0, %1, %2;" : "=r"(r) : "f"(hi), "f"(lo));
    return r;
}

// ---------------- attention SMEM layout ----------------
// Q rows padded to 272B (136 bf16): row offsets == 4 words mod 32 -> no ldsm conflicts
// g rows padded to 144B (72 bf16):  same property
#define QSTR 272
#define GSTR 144
#define OFF_QH 0
#define OFF_QL (128 * QSTR)                 // 34816
#define OFF_ST0 (2 * 128 * QSTR)            // 69632
#define ST_KH 0
#define ST_KL (64 * QSTR)                   // 17408
#define ST_GH (2 * 64 * QSTR)               // 34816
#define ST_GL (ST_GH + 128 * GSTR)          // 53248
#define STAGE_SZ (ST_GL + 128 * GSTR)       // 71680
#define ATTN_SMEM (OFF_ST0 + 2 * STAGE_SZ)  // 212992

// ================= projection: {theta,phi,g} = W @ x + b, bf16 hi/lo split ==
__global__ __launch_bounds__(256) void proj_kernel(
    const float* __restrict__ x,
    const float* __restrict__ th_w, const float* __restrict__ th_b,
    const float* __restrict__ ph_w, const float* __restrict__ ph_b,
    const float* __restrict__ gw,   const float* __restrict__ gb)
{
    __shared__ float Ws[32][68];
    __shared__ float Xs[32][68];
    const int bb = blockIdx.z;
    const int ot = blockIdx.y;
    const int n0 = blockIdx.x * 64;
    const int tid = threadIdx.x;
    const int tx = tid & 15, ty = tid >> 4;

    const float* W; const float* bias; int o0;
    if (ot < 2)      { W = th_w; bias = th_b; o0 = ot * 64; }
    else if (ot < 4) { W = ph_w; bias = ph_b; o0 = (ot - 2) * 64; }
    else             { W = gw;   bias = gb;   o0 = (ot - 4) * 64; }

    float acc[4][4] = {};
    for (int c0 = 0; c0 < CDIM; c0 += 32) {
        __syncthreads();
        for (int idx = tid; idx < 64 * 32; idx += 256) {
            int o = idx >> 5, c = idx & 31;
            Ws[c][o] = W[(o0 + o) * CDIM + c0 + c];
        }
        for (int idx = tid; idx < 32 * 64; idx += 256) {
            int c = idx >> 6, n = idx & 63;
            Xs[c][n] = x[((size_t)(bb * CDIM + c0 + c)) * NPIX + n0 + n];
        }
        __syncthreads();
        #pragma unroll
        for (int k = 0; k < 32; k++) {
            float4 wv = *(const float4*)&Ws[k][ty * 4];
            float4 xv = *(const float4*)&Xs[k][tx * 4];
            float wr[4] = {wv.x, wv.y, wv.z, wv.w};
            float xr[4] = {xv.x, xv.y, xv.z, xv.w};
            #pragma unroll
            for (int i = 0; i < 4; i++)
                #pragma unroll
                for (int j = 0; j < 4; j++)
                    acc[i][j] += wr[i] * xr[j];
        }
    }

    float bv[4];
    #pragma unroll
    for (int i = 0; i < 4; i++) bv[i] = bias[o0 + ty * 4 + i];

    if (ot < 4) {
        __nv_bfloat16* dh = (ot < 2) ? g_th_h : g_ph_h;
        __nv_bfloat16* dl = (ot < 2) ? g_th_l : g_ph_l;
        #pragma unroll
        for (int j = 0; j < 4; j++) {
            int n = n0 + tx * 4 + j;
            size_t base = ((size_t)bb * NPIX + n) * CIDIM + o0 + ty * 4;
            __nv_bfloat16 h[4], l[4];
            #pragma unroll
            for (int i = 0; i < 4; i++) {
                float v = acc[i][j] + bv[i];
                h[i] = __float2bfloat16(v);
                l[i] = __float2bfloat16(v - __bfloat162float(h[i]));
            }
            __nv_bfloat162 h01; h01.x = h[0]; h01.y = h[1];
            __nv_bfloat162 h23; h23.x = h[2]; h23.y = h[3];
            __nv_bfloat162 l01; l01.x = l[0]; l01.y = l[1];
            __nv_bfloat162 l23; l23.x = l[2]; l23.y = l[3];
            *(__nv_bfloat162*)&dh[base]     = h01;
            *(__nv_bfloat162*)&dh[base + 2] = h23;
            *(__nv_bfloat162*)&dl[base]     = l01;
            *(__nv_bfloat162*)&dl[base + 2] = l23;
        }
    } else {
        #pragma unroll
        for (int i = 0; i < 4; i++) {
            int o = o0 + ty * 4 + i;
            size_t base = ((size_t)bb * CIDIM + o) * NPIX + n0 + tx * 4;
            __nv_bfloat16 h[4], l[4];
            #pragma unroll
            for (int j = 0; j < 4; j++) {
                float v = acc[i][j] + bv[i];
                h[j] = __float2bfloat16(v);
                l[j] = __float2bfloat16(v - __bfloat162float(h[j]));
            }
            __nv_bfloat162 h01; h01.x = h[0]; h01.y = h[1];
            __nv_bfloat162 h23; h23.x = h[2]; h23.y = h[3];
            __nv_bfloat162 l01; l01.x = l[0]; l01.y = l[1];
            __nv_bfloat162 l23; l23.x = l[2]; l23.y = l[3];
            *(__nv_bfloat162*)&g_gm_h[base]     = h01;
            *(__nv_bfloat162*)&g_gm_h[base + 2] = h23;
            *(__nv_bfloat162*)&g_gm_l[base]     = l01;
            *(__nv_bfloat162*)&g_gm_l[base + 2] = l23;
        }
    }
}

// ================= HMMA flash attention =================
// 8 warps x 16 query rows; S = Qh*Kh^T + Qh*Kl^T + Ql*Kh^T; O += P*(Gh+Gl)
__global__ __launch_bounds__(256, 1) void attn_kernel()
{
    extern __shared__ char smem[];
    const uint32_t sb = smem_to_u32(smem);
    const int tid = threadIdx.x;
    const int w = tid >> 5, lane = tid & 31;
    const int bb = blockIdx.y;
    const int i0 = blockIdx.x * QT;

    const __nv_bfloat16* qh = g_th_h + ((size_t)bb * NPIX + i0) * CIDIM;
    const __nv_bfloat16* ql = g_th_l + ((size_t)bb * NPIX + i0) * CIDIM;
    const __nv_bfloat16* phb = g_ph_h + (size_t)bb * NPIX * CIDIM;
    const __nv_bfloat16* plb = g_ph_l + (size_t)bb * NPIX * CIDIM;
    const __nv_bfloat16* ghb = g_gm_h + (size_t)bb * CIDIM * NPIX;
    const __nv_bfloat16* glb = g_gm_l + (size_t)bb * CIDIM * NPIX;

    // ---- load Q tiles (persistent) ----
    #pragma unroll
    for (int t = 0; t < 8; t++) {
        int q = tid + t * 256;
        int r = q >> 4, c = q & 15;
        uint32_t d = sb + OFF_QH + r * QSTR + c * 16;
        cp16(d, qh + r * CIDIM + c * 8);
        cp16(d + (OFF_QL - OFF_QH), ql + r * CIDIM + c * 8);
    }

    auto load_stage = [&](int s, int j0) {
        uint32_t base = sb + OFF_ST0 + s * STAGE_SZ;
        #pragma unroll
        for (int t = 0; t < 4; t++) {           // K: 64 rows x 256B
            int q = tid + t * 256;
            int j = q >> 4, c = q & 15;
            uint32_t d = base + ST_KH + j * QSTR + c * 16;
            size_t g = (size_t)(j0 + j) * CIDIM + c * 8;
            cp16(d, phb + g);
            cp16(d + (ST_KL - ST_KH), plb + g);
        }
        #pragma unroll
        for (int t = 0; t < 4; t++) {           // G: 128 rows x 128B
            int q = tid + t * 256;
            int c = q >> 3, jc = q & 7;
            uint32_t d = base + ST_GH + c * GSTR + jc * 16;
            size_t g = (size_t)c * NPIX + j0 + jc * 8;
            cp16(d, ghb + g);
            cp16(d + (ST_GL - ST_GH), glb + g);
        }
    };
    load_stage(0, 0);
    CP_COMMIT();

    // ldmatrix lane addressing
    const uint32_t a_lane = (uint32_t)((lane & 15) * QSTR + (lane >> 4) * 16);
    const uint32_t aq_base = sb + OFF_QH + (uint32_t)(w * 16) * QSTR + a_lane;
    const uint32_t al_base = aq_base + (OFF_QL - OFF_QH);
    const int b_row  = (lane & 7) + ((lane >> 4) & 1) * 8;
    const int b_byte = ((lane >> 3) & 1) * 16;

    float oacc[16][4];
    #pragma unroll
    for (int i = 0; i < 16; i++)
        #pragma unroll
        for (int j = 0; j < 4; j++) oacc[i][j] = 0.f;
    float den0 = 0.f, den1 = 0.f;

    for (int jt = 0; jt < NJT; jt++) {
        const int s = jt & 1;
        if (jt + 1 < NJT) load_stage(s ^ 1, (jt + 1) * JT);
        CP_COMMIT();
        CP_WAIT1();
        __syncthreads();

        const uint32_t stb = sb + OFF_ST0 + s * STAGE_SZ;
        const uint32_t kB = stb + ST_KH + (uint32_t)(b_row * QSTR + b_byte);
        const uint32_t gB = stb + ST_GH + (uint32_t)(b_row * GSTR + b_byte);

        // ---- S phase ----
        float sacc[8][4];
        #pragma unroll
        for (int i = 0; i < 8; i++)
            #pragma unroll
            for (int j = 0; j < 4; j++) sacc[i][j] = 0.f;

        #pragma unroll
        for (int kk = 0; kk < 8; kk++) {
            uint32_t aq[4], al[4];
            ldsm4(aq_base + kk * 32, aq[0], aq[1], aq[2], aq[3]);
            ldsm4(al_base + kk * 32, al[0], al[1], al[2], al[3]);
            #pragma unroll
            for (int nb4 = 0; nb4 < 4; nb4++) {
                uint32_t bh0, bh1, bh2, bh3, bl0, bl1, bl2, bl3;
                uint32_t ka = kB + (uint32_t)(nb4 * 16 * QSTR + kk * 32);
                ldsm4(ka, bh0, bh1, bh2, bh3);
                ldsm4(ka + (ST_KL - ST_KH), bl0, bl1, bl2, bl3);
                mma16816(sacc[2 * nb4],     aq, bh0, bh1);
                mma16816(sacc[2 * nb4 + 1], aq, bh2, bh3);
                mma16816(sacc[2 * nb4],     al, bh0, bh1);
                mma16816(sacc[2 * nb4 + 1], al, bh2, bh3);
                mma16816(sacc[2 * nb4],     aq, bl0, bl1);
                mma16816(sacc[2 * nb4 + 1], aq, bl2, bl3);
            }
        }

        // ---- softmax numerators: P = exp(S), accumulate denominators ----
        uint32_t pf[4][4];
        #pragma unroll
        for (int nb = 0; nb < 8; nb++) {
            float e0 = __expf(sacc[nb][0]);
            float e1 = __expf(sacc[nb][1]);
            float e2 = __expf(sacc[nb][2]);
            float e3 = __expf(sacc[nb][3]);
            den0 += e0 + e1;
            den1 += e2 + e3;
            int kkj = nb >> 1, half = (nb & 1) * 2;
            pf[kkj][half]     = packbf2(e0, e1);
            pf[kkj][half + 1] = packbf2(e2, e3);
        }

        // ---- O += P @ G^T (hi + lo) ----
        #pragma unroll
        for (int kkj = 0; kkj < 4; kkj++) {
            #pragma unroll
            for (int cb = 0; cb < 8; cb++) {
                uint32_t bh0, bh1, bh2, bh3, bl0, bl1, bl2, bl3;
                uint32_t ga = gB + (uint32_t)(cb * 16 * GSTR + kkj * 32);
                ldsm4(ga, bh0, bh1, bh2, bh3);
                ldsm4(ga + (ST_GL - ST_GH), bl0, bl1, bl2, bl3);
                mma16816(oacc[2 * cb],     pf[kkj], bh0, bh1);
                mma16816(oacc[2 * cb + 1], pf[kkj], bh2, bh3);
                mma16816(oacc[2 * cb],     pf[kkj], bl0, bl1);
                mma16816(oacc[2 * cb + 1], pf[kkj], bl2, bl3);
            }
        }
        __syncthreads();   // all warps done reading stage s before it is refilled
    }

    // ---- denominators: reduce across the 4 lanes sharing a row ----
    den0 += __shfl_xor_sync(0xFFFFFFFF, den0, 1);
    den0 += __shfl_xor_sync(0xFFFFFFFF, den0, 2);
    den1 += __shfl_xor_sync(0xFFFFFFFF, den1, 1);
    den1 += __shfl_xor_sync(0xFFFFFFFF, den1, 2);
    const float inv0 = 1.0f / den0;
    const float inv1 = 1.0f / den1;

    // ---- write y[b][i][c] ----
    const int r0 = i0 + w * 16 + (lane >> 2);
    float* y0 = g_y + ((size_t)bb * NPIX + r0) * CIDIM + (lane & 3) * 2;
    float* y1 = y0 + 8 * CIDIM;
    #pragma unroll
    for (int cb = 0; cb < 16; cb++) {
        float2 v0 = make_float2(oacc[cb][0] * inv0, oacc[cb][1] * inv0);
        float2 v1 = make_float2(oacc[cb][2] * inv1, oacc[cb][3] * inv1);
        *(float2*)(y0 + cb * 8) = v0;
        *(float2*)(y1 + cb * 8) = v1;
    }
}

// ================= out = W_w @ y + W_b + x =================
__global__ __launch_bounds__(256) void outproj_kernel(
    const float* __restrict__ Ww, const float* __restrict__ Wb,
    const float* __restrict__ x, float* __restrict__ out)
{
    __shared__ float As[64][68];
    __shared__ float Ys[64][68];
    const int bb = blockIdx.z;
    const int c0 = blockIdx.y * 64;
    const int n0 = blockIdx.x * 64;
    const int tid = threadIdx.x;
    const int tx = tid & 15, ty = tid >> 4;

    float acc[4][4] = {};
    for (int k0 = 0; k0 < CIDIM; k0 += 64) {
        __syncthreads();
        for (int idx = tid; idx < 64 * 64; idx += 256) {
            int r = idx >> 6, k = idx & 63;
            As[k][r] = Ww[(c0 + r) * CIDIM + k0 + k];
        }
        for (int idx = tid; idx < 64 * 64; idx += 256) {
            int n = idx >> 6, k = idx & 63;
            Ys[k][n] = g_y[(((size_t)bb * NPIX) + n0 + n) * CIDIM + k0 + k];
        }
        __syncthreads();
        #pragma unroll 8
        for (int k = 0; k < 64; k++) {
            float4 av = *(const float4*)&As[k][ty * 4];
            float4 yv = *(const float4*)&Ys[k][tx * 4];
            float ar[4] = {av.x, av.y, av.z, av.w};
            float yr[4] = {yv.x, yv.y, yv.z, yv.w};
            #pragma unroll
            for (int i = 0; i < 4; i++)
                #pragma unroll
                for (int j = 0; j < 4; j++)
                    acc[i][j] += ar[i] * yr[j];
        }
    }
    #pragma unroll
    for (int i = 0; i < 4; i++) {
        int c = c0 + ty * 4 + i;
        float bv = Wb[c];
        size_t base = (((size_t)bb * CDIM) + c) * NPIX + n0 + tx * 4;
        float4 xv = *(const float4*)&x[base];
        float4 st = make_float4(acc[i][0] + bv + xv.x, acc[i][1] + bv + xv.y,
                                acc[i][2] + bv + xv.z, acc[i][3] + bv + xv.w);
        *(float4*)&out[base] = st;
    }
}

extern "C" void kernel_launch(void* const* d_in, const int* in_sizes, int n_in,
                              void* d_out, int out_size) {
    const float* x    = (const float*)d_in[0];
    const float* g_w  = (const float*)d_in[1];
    const float* g_b  = (const float*)d_in[2];
    const float* th_w = (const float*)d_in[3];
    const float* th_b = (const float*)d_in[4];
    const float* ph_w = (const float*)d_in[5];
    const float* ph_b = (const float*)d_in[6];
    const float* W_w  = (const float*)d_in[7];
    const float* W_b  = (const float*)d_in[8];
    float* out = (float*)d_out;

    cudaFuncSetAttribute(attn_kernel,
                         cudaFuncAttributeMaxDynamicSharedMemorySize, ATTN_SMEM);

    proj_kernel<<<dim3(NPIX / 64, 6, BATCH), 256>>>(x, th_w, th_b, ph_w, ph_b, g_w, g_b);
    attn_kernel<<<dim3(NPIX / QT, BATCH), 256, ATTN_SMEM>>>();
    outproj_kernel<<<dim3(NPIX / 64, CDIM / 64, BATCH), 256>>>(W_w, W_b, x, out);
}

// round 6
// speedup vs baseline: 5.7428x; 1.4633x over previous
#include <cuda_runtime.h>
#include <cuda_bf16.h>
#include <cstdint>
#include <cstddef>

#define BATCH 8
#define CDIM 256
#define CIDIM 128
#define NPIX 4096
#define QT 128
#define JT 64
#define NJT (NPIX / JT)

// ---------------- scratch (__device__ globals; no allocation) ----------------
static __device__ __nv_bfloat16 g_x_h [BATCH * CDIM * NPIX];   // x split  [B][C][N]
static __device__ __nv_bfloat16 g_x_l [BATCH * CDIM * NPIX];
static __device__ __nv_bfloat16 g_wsp_h[4 * 32768];            // th,ph,g,W_w split
static __device__ __nv_bfloat16 g_wsp_l[4 * 32768];
static __device__ __nv_bfloat16 g_th_h[BATCH * NPIX * CIDIM];  // [B][N][CI]
static __device__ __nv_bfloat16 g_th_l[BATCH * NPIX * CIDIM];
static __device__ __nv_bfloat16 g_ph_h[BATCH * NPIX * CIDIM];
static __device__ __nv_bfloat16 g_ph_l[BATCH * NPIX * CIDIM];
static __device__ __nv_bfloat16 g_gm_h[BATCH * CIDIM * NPIX];  // [B][CI][N]
static __device__ __nv_bfloat16 g_y_h [BATCH * NPIX * CIDIM];  // [B][N][CI]
static __device__ __nv_bfloat16 g_y_l [BATCH * NPIX * CIDIM];

// ---------------- PTX helpers (sm_80+ family-portable) ----------------
__device__ __forceinline__ uint32_t smem_to_u32(const void* p) {
    uint32_t a;
    asm("{ .reg .u64 t; cvta.to.shared.u64 t, %1; cvt.u32.u64 %0, t; }"
        : "=r"(a) : "l"(p));
    return a;
}
__device__ __forceinline__ void cp16(uint32_t dst, const void* src) {
    asm volatile("cp.async.cg.shared.global [%0], [%1], 16;" :: "r"(dst), "l"(src) : "memory");
}
#define CP_COMMIT() asm volatile("cp.async.commit_group;" ::: "memory")
#define CP_WAIT1()  asm volatile("cp.async.wait_group 1;" ::: "memory")
#define CP_WAIT0()  asm volatile("cp.async.wait_group 0;" ::: "memory")

__device__ __forceinline__ void ldsm4(uint32_t a, uint32_t& r0, uint32_t& r1,
                                      uint32_t& r2, uint32_t& r3) {
    asm volatile("ldmatrix.sync.aligned.m8n8.x4.shared.b16 {%0,%1,%2,%3}, [%4];"
                 : "=r"(r0), "=r"(r1), "=r"(r2), "=r"(r3) : "r"(a));
}
__device__ __forceinline__ void ldsm4t(uint32_t a, uint32_t& r0, uint32_t& r1,
                                       uint32_t& r2, uint32_t& r3) {
    asm volatile("ldmatrix.sync.aligned.m8n8.x4.trans.shared.b16 {%0,%1,%2,%3}, [%4];"
                 : "=r"(r0), "=r"(r1), "=r"(r2), "=r"(r3) : "r"(a));
}
__device__ __forceinline__ void mma16816(float* d, const uint32_t* a,
                                         uint32_t b0, uint32_t b1) {
    asm volatile("mma.sync.aligned.m16n8k16.row.col.f32.bf16.bf16.f32 "
                 "{%0,%1,%2,%3}, {%4,%5,%6,%7}, {%8,%9}, {%0,%1,%2,%3};"
                 : "+f"(d[0]), "+f"(d[1]), "+f"(d[2]), "+f"(d[3])
                 : "r"(a[0]), "r"(a[1]), "r"(a[2]), "r"(a[3]), "r"(b0), "r"(b1));
}
__device__ __forceinline__ uint32_t packbf2(float lo, float hi) {
    uint32_t r;
    asm("cvt.rn.satfinite.bf16x2.f32 %0, %1, %2;" : "=r"(r) : "f"(hi), "f"(lo));
    return r;
}
// hi/lo split of a float pair, packed to two bf16x2 words
__device__ __forceinline__ void split2(float v0, float v1, uint32_t& h, uint32_t& l) {
    __nv_bfloat16 h0 = __float2bfloat16(v0), h1 = __float2bfloat16(v1);
    float f0 = __bfloat162float(h0), f1 = __bfloat162float(h1);
    __nv_bfloat162 hh; hh.x = h0; hh.y = h1;
    __nv_bfloat162 ll; ll.x = __float2bfloat16(v0 - f0); ll.y = __float2bfloat16(v1 - f1);
    h = *(uint32_t*)&hh;
    l = *(uint32_t*)&ll;
}

// ================= convert kernels =================
__global__ __launch_bounds__(256) void xsplit_kernel(const float* __restrict__ x) {
    int i = blockIdx.x * 256 + threadIdx.x;          // over float4 units
    float4 v = ((const float4*)x)[i];
    uint32_t h01, l01, h23, l23;
    split2(v.x, v.y, h01, l01);
    split2(v.z, v.w, h23, l23);
    uint2 hv = make_uint2(h01, h23);
    uint2 lv = make_uint2(l01, l23);
    ((uint2*)g_x_h)[i] = hv;
    ((uint2*)g_x_l)[i] = lv;
}
__global__ __launch_bounds__(256) void wsplit_kernel(
    const float* __restrict__ thw, const float* __restrict__ phw,
    const float* __restrict__ gw,  const float* __restrict__ Ww) {
    int idx = blockIdx.x * 256 + threadIdx.x;        // 0..131071
    int seg = idx >> 15, loc = idx & 32767;
    const float* src = (seg == 0) ? thw : (seg == 1) ? phw : (seg == 2) ? gw : Ww;
    float v = src[loc];
    __nv_bfloat16 h = __float2bfloat16(v);
    g_wsp_h[idx] = h;
    g_wsp_l[idx] = __float2bfloat16(v - __bfloat162float(h));
}

// ================= HMMA projection =================
// flavor 0/1 (theta/phi): out[pix][ci] = x^T W^T ; A = x (trans), B = W (non-trans)
// flavor 2   (g):         out[ci][pix]          ; A = W,         B = x (trans)
#define PJ_XSTR 272
#define PJ_WSTR 144
#define PJ_XH 0
#define PJ_XL 17408
#define PJ_WH 34816
#define PJ_WL 53248
#define PJ_STAGE 71680
#define PROJ_SMEM (2 * PJ_STAGE)

__global__ __launch_bounds__(256, 1) void proj_kernel(
    const float* __restrict__ th_b, const float* __restrict__ ph_b,
    const float* __restrict__ g_b)
{
    extern __shared__ char smem[];
    const uint32_t sb = smem_to_u32(smem);
    const int tid = threadIdx.x;
    const int w = tid >> 5, lane = tid & 31;
    const int wm = w & 3, wn = w >> 2;               // 4 x 2 warp grid
    const int flavor = blockIdx.y;
    const int pt = blockIdx.x;
    const int bb = pt >> 5;
    const int n0 = (pt & 31) * 128;

    const __nv_bfloat16* xh = g_x_h + (size_t)bb * CDIM * NPIX + n0;
    const __nv_bfloat16* xl = g_x_l + (size_t)bb * CDIM * NPIX + n0;
    const __nv_bfloat16* wh = g_wsp_h + flavor * 32768;
    const __nv_bfloat16* wl = g_wsp_l + flavor * 32768;

    auto load_chunk = [&](int s, int k0) {
        uint32_t base = sb + s * PJ_STAGE;
        #pragma unroll
        for (int t = 0; t < 4; t++) {                // x: 64 k-rows x 256B
            int q = tid + t * 256;
            int k = q >> 4, j = q & 15;
            uint32_t d = base + PJ_XH + k * PJ_XSTR + j * 16;
            size_t g = (size_t)(k0 + k) * NPIX + j * 8;
            cp16(d, xh + g);
            cp16(d + (PJ_XL - PJ_XH), xl + g);
        }
        #pragma unroll
        for (int t = 0; t < 4; t++) {                // W: 128 o-rows x 128B
            int q = tid + t * 256;
            int o = q >> 3, j = q & 7;
            uint32_t d = base + PJ_WH + o * PJ_WSTR + j * 16;
            size_t g = (size_t)o * CDIM + k0 + j * 8;
            cp16(d, wh + g);
            cp16(d + (PJ_WL - PJ_WH), wl + g);
        }
    };
    load_chunk(0, 0);
    CP_COMMIT();

    // ldmatrix base offsets (within stage)
    uint32_t a_base, b_base, a_m16, a_kk, b_ng, b_kk, a_lo, b_lo;
    if (flavor < 2) {
        // A = x via trans (rows=k, cols=pix): row=(l&7)+((l>>4)&1)*8, byte=((l>>3)&1)*16
        a_base = PJ_XH + (uint32_t)(((lane & 7) + ((lane >> 4) & 1) * 8) * PJ_XSTR
                                    + wm * 64 + ((lane >> 3) & 1) * 16);
        a_m16 = 32;               a_kk = 16 * PJ_XSTR;  a_lo = PJ_XL - PJ_XH;
        // B = W non-trans (rows=o, cols=k)
        b_base = PJ_WH + (uint32_t)((wn * 64 + (lane & 7) + ((lane >> 4) & 1) * 8) * PJ_WSTR
                                    + ((lane >> 3) & 1) * 16);
        b_ng = 16 * PJ_WSTR;      b_kk = 32;            b_lo = PJ_WL - PJ_WH;
    } else {
        // A = W non-trans (rows=o, cols=k)
        a_base = PJ_WH + (uint32_t)((wm * 32 + (lane & 15)) * PJ_WSTR + (lane >> 4) * 16);
        a_m16 = 16 * PJ_WSTR;     a_kk = 32;            a_lo = PJ_WL - PJ_WH;
        // B = x via trans (rows=k, cols=pix): row=(l&7)+((l>>3)&1)*8, byte=(l>>4)*16
        b_base = PJ_XH + (uint32_t)(((lane & 7) + ((lane >> 3) & 1) * 8) * PJ_XSTR
                                    + wn * 128 + (lane >> 4) * 16);
        b_ng = 32;                b_kk = 16 * PJ_XSTR;  b_lo = PJ_XL - PJ_XH;
    }

    float acc[2][8][4];
    #pragma unroll
    for (int i = 0; i < 2; i++)
        #pragma unroll
        for (int j = 0; j < 8; j++)
            #pragma unroll
            for (int q = 0; q < 4; q++) acc[i][j][q] = 0.f;

    #pragma unroll 1
    for (int ch = 0; ch < 4; ch++) {
        if (ch < 3) load_chunk((ch + 1) & 1, (ch + 1) * 64);
        CP_COMMIT();
        CP_WAIT1();
        __syncthreads();
        const uint32_t stb = sb + (ch & 1) * PJ_STAGE;
        #pragma unroll
        for (int kk = 0; kk < 4; kk++) {
            uint32_t aH[2][4], aL[2][4];
            #pragma unroll
            for (int m = 0; m < 2; m++) {
                uint32_t aa = stb + a_base + kk * a_kk + m * a_m16;
                if (flavor < 2) {
                    ldsm4t(aa,        aH[m][0], aH[m][1], aH[m][2], aH[m][3]);
                    ldsm4t(aa + a_lo, aL[m][0], aL[m][1], aL[m][2], aL[m][3]);
                } else {
                    ldsm4(aa,         aH[m][0], aH[m][1], aH[m][2], aH[m][3]);
                    ldsm4(aa + a_lo,  aL[m][0], aL[m][1], aL[m][2], aL[m][3]);
                }
            }
            #pragma unroll
            for (int ng = 0; ng < 4; ng++) {
                uint32_t bh0, bh1, bh2, bh3, bl0, bl1, bl2, bl3;
                uint32_t ba = stb + b_base + kk * b_kk + ng * b_ng;
                if (flavor < 2) {
                    ldsm4(ba,         bh0, bh1, bh2, bh3);
                    ldsm4(ba + b_lo,  bl0, bl1, bl2, bl3);
                } else {
                    ldsm4t(ba,        bh0, bh1, bh2, bh3);
                    ldsm4t(ba + b_lo, bl0, bl1, bl2, bl3);
                }
                #pragma unroll
                for (int m = 0; m < 2; m++) {
                    mma16816(acc[m][2 * ng],     aH[m], bh0, bh1);
                    mma16816(acc[m][2 * ng + 1], aH[m], bh2, bh3);
                    mma16816(acc[m][2 * ng],     aL[m], bh0, bh1);
                    mma16816(acc[m][2 * ng + 1], aL[m], bh2, bh3);
                    mma16816(acc[m][2 * ng],     aH[m], bl0, bl1);
                    mma16816(acc[m][2 * ng + 1], aH[m], bl2, bl3);
                }
            }
        }
        __syncthreads();
    }

    if (flavor < 2) {
        __nv_bfloat16* dh = (flavor == 0) ? g_th_h : g_ph_h;
        __nv_bfloat16* dl = (flavor == 0) ? g_th_l : g_ph_l;
        const float* bias = (flavor == 0) ? th_b : ph_b;
        const int m_row = wm * 32 + (lane >> 2);
        const int o_col = wn * 64 + (lane & 3) * 2;
        #pragma unroll
        for (int m = 0; m < 2; m++) {
            #pragma unroll
            for (int n8 = 0; n8 < 8; n8++) {
                float2 bv = *(const float2*)&bias[o_col + n8 * 8];
                int pix = n0 + m_row + m * 16;
                size_t a0 = ((size_t)bb * NPIX + pix) * CIDIM + o_col + n8 * 8;
                uint32_t h, l;
                split2(acc[m][n8][0] + bv.x, acc[m][n8][1] + bv.y, h, l);
                *(uint32_t*)&dh[a0] = h;
                *(uint32_t*)&dl[a0] = l;
                size_t a1 = a0 + (size_t)8 * CIDIM;
                split2(acc[m][n8][2] + bv.x, acc[m][n8][3] + bv.y, h, l);
                *(uint32_t*)&dh[a1] = h;
                *(uint32_t*)&dl[a1] = l;
            }
        }
    } else {
        const int o_row = wm * 32 + (lane >> 2);
        const int p_col = wn * 64 + (lane & 3) * 2;
        #pragma unroll
        for (int m = 0; m < 2; m++) {
            int o = o_row + m * 16;
            float b0 = g_b[o], b1 = g_b[o + 8];
            #pragma unroll
            for (int n8 = 0; n8 < 8; n8++) {
                size_t a0 = ((size_t)bb * CIDIM + o) * NPIX + n0 + p_col + n8 * 8;
                *(uint32_t*)&g_gm_h[a0] =
                    packbf2(acc[m][n8][0] + b0, acc[m][n8][1] + b0);
                size_t a1 = a0 + (size_t)8 * NPIX;
                *(uint32_t*)&g_gm_h[a1] =
                    packbf2(acc[m][n8][2] + b1, acc[m][n8][3] + b1);
            }
        }
    }
}

// ================= HMMA flash attention =================
#define QSTR 272
#define GSTR 144
#define OFF_QH 0
#define OFF_QL (128 * QSTR)
#define OFF_ST0 (2 * 128 * QSTR)            // 69632
#define ST_KH 0
#define ST_KL (64 * QSTR)                   // 17408
#define ST_GH (2 * 64 * QSTR)               // 34816
#define STAGE_SZ (ST_GH + 128 * GSTR)       // 53248
#define ATTN_SMEM (OFF_ST0 + 2 * STAGE_SZ)  // 176128

__global__ __launch_bounds__(256, 1) void attn_kernel()
{
    extern __shared__ char smem[];
    const uint32_t sb = smem_to_u32(smem);
    const int tid = threadIdx.x;
    const int w = tid >> 5, lane = tid & 31;
    const int bb = blockIdx.y;
    const int i0 = blockIdx.x * QT;

    const __nv_bfloat16* qh = g_th_h + ((size_t)bb * NPIX + i0) * CIDIM;
    const __nv_bfloat16* ql = g_th_l + ((size_t)bb * NPIX + i0) * CIDIM;
    const __nv_bfloat16* phb = g_ph_h + (size_t)bb * NPIX * CIDIM;
    const __nv_bfloat16* plb = g_ph_l + (size_t)bb * NPIX * CIDIM;
    const __nv_bfloat16* ghb = g_gm_h + (size_t)bb * CIDIM * NPIX;

    #pragma unroll
    for (int t = 0; t < 8; t++) {
        int q = tid + t * 256;
        int r = q >> 4, c = q & 15;
        uint32_t d = sb + OFF_QH + r * QSTR + c * 16;
        cp16(d, qh + r * CIDIM + c * 8);
        cp16(d + (OFF_QL - OFF_QH), ql + r * CIDIM + c * 8);
    }

    auto load_stage = [&](int s, int j0) {
        uint32_t base = sb + OFF_ST0 + s * STAGE_SZ;
        #pragma unroll
        for (int t = 0; t < 4; t++) {           // K hi/lo: 64 rows x 256B
            int q = tid + t * 256;
            int j = q >> 4, c = q & 15;
            uint32_t d = base + ST_KH + j * QSTR + c * 16;
            size_t g = (size_t)(j0 + j) * CIDIM + c * 8;
            cp16(d, phb + g);
            cp16(d + (ST_KL - ST_KH), plb + g);
        }
        #pragma unroll
        for (int t = 0; t < 4; t++) {           // G hi: 128 rows x 128B
            int q = tid + t * 256;
            int c = q >> 3, jc = q & 7;
            cp16(base + ST_GH + c * GSTR + jc * 16,
                 ghb + (size_t)c * NPIX + j0 + jc * 8);
        }
    };
    load_stage(0, 0);
    CP_COMMIT();

    const uint32_t a_lane = (uint32_t)((lane & 15) * QSTR + (lane >> 4) * 16);
    const uint32_t aq_base = sb + OFF_QH + (uint32_t)(w * 16) * QSTR + a_lane;
    const uint32_t al_base = aq_base + (OFF_QL - OFF_QH);
    const int b_row  = (lane & 7) + ((lane >> 4) & 1) * 8;
    const int b_byte = ((lane >> 3) & 1) * 16;

    float oacc[16][4];
    #pragma unroll
    for (int i = 0; i < 16; i++)
        #pragma unroll
        for (int j = 0; j < 4; j++) oacc[i][j] = 0.f;
    float den0 = 0.f, den1 = 0.f;

    for (int jt = 0; jt < NJT; jt++) {
        const int s = jt & 1;
        if (jt + 1 < NJT) load_stage(s ^ 1, (jt + 1) * JT);
        CP_COMMIT();
        CP_WAIT1();
        __syncthreads();

        const uint32_t stb = sb + OFF_ST0 + s * STAGE_SZ;
        const uint32_t kB = stb + ST_KH + (uint32_t)(b_row * QSTR + b_byte);
        const uint32_t gB = stb + ST_GH + (uint32_t)(b_row * GSTR + b_byte);

        float sacc[8][4];
        #pragma unroll
        for (int i = 0; i < 8; i++)
            #pragma unroll
            for (int j = 0; j < 4; j++) sacc[i][j] = 0.f;

        #pragma unroll
        for (int kk = 0; kk < 8; kk++) {
            uint32_t aq[4], al[4];
            ldsm4(aq_base + kk * 32, aq[0], aq[1], aq[2], aq[3]);
            ldsm4(al_base + kk * 32, al[0], al[1], al[2], al[3]);
            #pragma unroll
            for (int nb4 = 0; nb4 < 4; nb4++) {
                uint32_t bh0, bh1, bh2, bh3, bl0, bl1, bl2, bl3;
                uint32_t ka = kB + (uint32_t)(nb4 * 16 * QSTR + kk * 32);
                ldsm4(ka, bh0, bh1, bh2, bh3);
                ldsm4(ka + (ST_KL - ST_KH), bl0, bl1, bl2, bl3);
                mma16816(sacc[2 * nb4],     aq, bh0, bh1);
                mma16816(sacc[2 * nb4 + 1], aq, bh2, bh3);
                mma16816(sacc[2 * nb4],     al, bh0, bh1);
                mma16816(sacc[2 * nb4 + 1], al, bh2, bh3);
                mma16816(sacc[2 * nb4],     aq, bl0, bl1);
                mma16816(sacc[2 * nb4 + 1], aq, bl2, bl3);
            }
        }

        uint32_t pf[4][4];
        #pragma unroll
        for (int nb = 0; nb < 8; nb++) {
            float e0 = __expf(sacc[nb][0]);
            float e1 = __expf(sacc[nb][1]);
            float e2 = __expf(sacc[nb][2]);
            float e3 = __expf(sacc[nb][3]);
            den0 += e0 + e1;
            den1 += e2 + e3;
            int kkj = nb >> 1, half = (nb & 1) * 2;
            pf[kkj][half]     = packbf2(e0, e1);
            pf[kkj][half + 1] = packbf2(e2, e3);
        }

        #pragma unroll
        for (int kkj = 0; kkj < 4; kkj++) {
            #pragma unroll
            for (int cb = 0; cb < 8; cb++) {
                uint32_t bh0, bh1, bh2, bh3;
                ldsm4(gB + (uint32_t)(cb * 16 * GSTR + kkj * 32), bh0, bh1, bh2, bh3);
                mma16816(oacc[2 * cb],     pf[kkj], bh0, bh1);
                mma16816(oacc[2 * cb + 1], pf[kkj], bh2, bh3);
            }
        }
        __syncthreads();
    }

    den0 += __shfl_xor_sync(0xFFFFFFFF, den0, 1);
    den0 += __shfl_xor_sync(0xFFFFFFFF, den0, 2);
    den1 += __shfl_xor_sync(0xFFFFFFFF, den1, 1);
    den1 += __shfl_xor_sync(0xFFFFFFFF, den1, 2);
    const float inv0 = 1.0f / den0;
    const float inv1 = 1.0f / den1;

    // write y hi/lo bf16 [B][N][CI]
    const int r0 = i0 + w * 16 + (lane >> 2);
    size_t base0 = ((size_t)bb * NPIX + r0) * CIDIM + (lane & 3) * 2;
    #pragma unroll
    for (int cb = 0; cb < 16; cb++) {
        uint32_t h, l;
        split2(oacc[cb][0] * inv0, oacc[cb][1] * inv0, h, l);
        *(uint32_t*)&g_y_h[base0 + cb * 8] = h;
        *(uint32_t*)&g_y_l[base0 + cb * 8] = l;
        split2(oacc[cb][2] * inv1, oacc[cb][3] * inv1, h, l);
        *(uint32_t*)&g_y_h[base0 + 8 * CIDIM + cb * 8] = h;
        *(uint32_t*)&g_y_l[base0 + 8 * CIDIM + cb * 8] = l;
    }
}

// ================= HMMA outproj: out = W_w @ y + b + x =================
#define OP_STR 272
#define OP_WH 0
#define OP_WL 34816
#define OP_YH 69632
#define OP_YL 104448
#define OP_SMEM 139264

__global__ __launch_bounds__(256, 1) void outproj_kernel(
    const float* __restrict__ Wb, const float* __restrict__ x,
    float* __restrict__ out)
{
    extern __shared__ char smem[];
    const uint32_t sb = smem_to_u32(smem);
    const int tid = threadIdx.x;
    const int w = tid >> 5, lane = tid & 31;
    const int wm = w & 3, wn = w >> 2;
    const int pt = blockIdx.x;
    const int c0 = blockIdx.y * 128;
    const int bb = pt >> 5;
    const int n0 = (pt & 31) * 128;

    const __nv_bfloat16* wwh = g_wsp_h + 3 * 32768;
    const __nv_bfloat16* wwl = g_wsp_l + 3 * 32768;
    const __nv_bfloat16* yh = g_y_h + ((size_t)bb * NPIX + n0) * CIDIM;
    const __nv_bfloat16* yl = g_y_l + ((size_t)bb * NPIX + n0) * CIDIM;

    #pragma unroll
    for (int t = 0; t < 8; t++) {              // W_w: 128 c-rows x 256B
        int q = tid + t * 256;
        int r = q >> 4, j = q & 15;
        uint32_t d = sb + OP_WH + r * OP_STR + j * 16;
        size_t g = (size_t)(c0 + r) * CIDIM + j * 8;
        cp16(d, wwh + g);
        cp16(d + (OP_WL - OP_WH), wwl + g);
    }
    #pragma unroll
    for (int t = 0; t < 8; t++) {              // y: 128 n-rows x 256B
        int q = tid + t * 256;
        int r = q >> 4, j = q & 15;
        uint32_t d = sb + OP_YH + r * OP_STR + j * 16;
        size_t g = (size_t)r * CIDIM + j * 8;
        cp16(d, yh + g);
        cp16(d + (OP_YL - OP_YH), yl + g);
    }
    CP_COMMIT();
    CP_WAIT0();
    __syncthreads();

    const uint32_t a_base = sb + OP_WH +
        (uint32_t)((wm * 32 + (lane & 15)) * OP_STR + (lane >> 4) * 16);
    const uint32_t b_base = sb + OP_YH +
        (uint32_t)((wn * 64 + (lane & 7) + ((lane >> 4) & 1) * 8) * OP_STR
                   + ((lane >> 3) & 1) * 16);

    float acc[2][8][4];
    #pragma unroll
    for (int i = 0; i < 2; i++)
        #pragma unroll
        for (int j = 0; j < 8; j++)
            #pragma unroll
            for (int q = 0; q < 4; q++) acc[i][j][q] = 0.f;

    #pragma unroll
    for (int kk = 0; kk < 8; kk++) {
        uint32_t aH[2][4], aL[2][4];
        #pragma unroll
        for (int m = 0; m < 2; m++) {
            uint32_t aa = a_base + kk * 32 + m * 16 * OP_STR;
            ldsm4(aa,                  aH[m][0], aH[m][1], aH[m][2], aH[m][3]);
            ldsm4(aa + (OP_WL - OP_WH), aL[m][0], aL[m][1], aL[m][2], aL[m][3]);
        }
        #pragma unroll
        for (int ng = 0; ng < 4; ng++) {
            uint32_t bh0, bh1, bh2, bh3, bl0, bl1, bl2, bl3;
            uint32_t ba = b_base + kk * 32 + ng * 16 * OP_STR;
            ldsm4(ba,                  bh0, bh1, bh2, bh3);
            ldsm4(ba + (OP_YL - OP_YH), bl0, bl1, bl2, bl3);
            #pragma unroll
            for (int m = 0; m < 2; m++) {
                mma16816(acc[m][2 * ng],     aH[m], bh0, bh1);
                mma16816(acc[m][2 * ng + 1], aH[m], bh2, bh3);
                mma16816(acc[m][2 * ng],     aL[m], bh0, bh1);
                mma16816(acc[m][2 * ng + 1], aL[m], bh2, bh3);
                mma16816(acc[m][2 * ng],     aH[m], bl0, bl1);
                mma16816(acc[m][2 * ng + 1], aH[m], bl2, bl3);
            }
        }
    }

    const int c_row = c0 + wm * 32 + (lane >> 2);
    const int p_col = wn * 64 + (lane & 3) * 2;
    #pragma unroll
    for (int m = 0; m < 2; m++) {
        int c = c_row + m * 16;
        float b0 = Wb[c], b1 = Wb[c + 8];
        #pragma unroll
        for (int n8 = 0; n8 < 8; n8++) {
            size_t a0 = ((size_t)bb * CDIM + c) * NPIX + n0 + p_col + n8 * 8;
            float2 xv = *(const float2*)&x[a0];
            *(float2*)&out[a0] = make_float2(acc[m][n8][0] + b0 + xv.x,
                                             acc[m][n8][1] + b0 + xv.y);
            size_t a1 = a0 + (size_t)8 * NPIX;
            float2 xv1 = *(const float2*)&x[a1];
            *(float2*)&out[a1] = make_float2(acc[m][n8][2] + b1 + xv1.x,
                                             acc[m][n8][3] + b1 + xv1.y);
        }
    }
}

extern "C" void kernel_launch(void* const* d_in, const int* in_sizes, int n_in,
                              void* d_out, int out_size) {
    const float* x    = (const float*)d_in[0];
    const float* g_w  = (const float*)d_in[1];
    const float* g_b  = (const float*)d_in[2];
    const float* th_w = (const float*)d_in[3];
    const float* th_b = (const float*)d_in[4];
    const float* ph_w = (const float*)d_in[5];
    const float* ph_b = (const float*)d_in[6];
    const float* W_w  = (const float*)d_in[7];
    const float* W_b  = (const float*)d_in[8];
    float* out = (float*)d_out;

    cudaFuncSetAttribute(proj_kernel,
                         cudaFuncAttributeMaxDynamicSharedMemorySize, PROJ_SMEM);
    cudaFuncSetAttribute(attn_kernel,
                         cudaFuncAttributeMaxDynamicSharedMemorySize, ATTN_SMEM);
    cudaFuncSetAttribute(outproj_kernel,
                         cudaFuncAttributeMaxDynamicSharedMemorySize, OP_SMEM);

    xsplit_kernel<<<BATCH * CDIM * NPIX / 4 / 256, 256>>>(x);
    wsplit_kernel<<<4 * 32768 / 256, 256>>>(th_w, ph_w, g_w, W_w);
    proj_kernel<<<dim3(BATCH * NPIX / 128, 3), 256, PROJ_SMEM>>>(th_b, ph_b, g_b);
    attn_kernel<<<dim3(NPIX / QT, BATCH), 256, ATTN_SMEM>>>();
    outproj_kernel<<<dim3(BATCH * NPIX / 128, CDIM / 128), 256, OP_SMEM>>>(W_b, x, out);
}